// round 4
// baseline (speedup 1.0000x reference)
#include <cuda_runtime.h>
#include <cuda_bf16.h>

// out[n,c,k,l] = x[n,c,oh,ow] - xpad[n,c,oh+i,ow+j]; K=7, PAD=3
// x:(16,64,56,56) f32 -> out:(16,64,49,3136) f32. HBM-write-bound (~629MB out).
//
// R3: __launch_bounds__(256,5) to raise residency 4->5 CTAs/SM (deeper store
// MLP, staging bubbles covered); inner loop restructured to keep the live
// register set under the 51-reg cap without spills.

#define PLANE   3136        // 56*56
#define TPITCH  64          // padded pitch (16B-aligned rows)
#define TROWS   62          // 56 + 2*3
#define NTHREADS 256
#define NGROUPS 784         // 3136 / 4 float4-groups per k

__global__ __launch_bounds__(NTHREADS, 5)
void Subtraction_68212670595965_kernel(const float* __restrict__ x,
                                       float* __restrict__ out) {
    __shared__ float tile[TROWS * TPITCH];   // 62*64*4 = 15872 B

    const int nc = blockIdx.x;               // n*64 + c, 0..1023
    const float* __restrict__ xin = x + (size_t)nc * PLANE;
    float* __restrict__ outb = out + (size_t)nc * 49 * PLANE;

    const int tid = threadIdx.x;

    // Stage padded plane (zero halo + zero cols 62..63 of the pitch).
    #pragma unroll 1
    for (int idx = tid; idx < TROWS * TPITCH; idx += NTHREADS) {
        const int r = idx >> 6;        // /64
        const int c = idx & 63;
        float v = 0.0f;
        if (r >= 3 && r < 59 && c >= 3 && c < 59)
            v = xin[(r - 3) * 56 + (c - 3)];
        tile[idx] = v;
    }
    __syncthreads();

    // Groups of 4 consecutive l. 784 groups; 14 groups per output row.
    #pragma unroll 1
    for (int g = tid; g < NGROUPS; g += NTHREADS) {
        const int oh  = g / 14;
        const int ow4 = (g - oh * 14) * 4;          // 0,4,...,52

        // centers: x[oh][ow4..ow4+3] = tile[(oh+3)*64 + ow4+3 .. +6]
        const int cbase = (oh + 3) * TPITCH + ow4 + 3;
        const float c0 = tile[cbase + 0];
        const float c1 = tile[cbase + 1];
        const float c2 = tile[cbase + 2];
        const float c3 = tile[cbase + 3];

        float* __restrict__ op = outb + 4 * g;

        #pragma unroll
        for (int i = 0; i < 7; ++i) {
            const float4* rp =
                reinterpret_cast<const float4*>(&tile[(oh + i) * TPITCH + ow4]);
            const float4 a = rp[0];
            const float4 b = rp[1];
            const float4 cq = rp[2];
            float* __restrict__ orow = op + i * 7 * PLANE;

            // j = 0..3 use {a, b}; j = 4..6 additionally use cq.
            {   // j=0
                float4 o = {c0 - a.x, c1 - a.y, c2 - a.z, c3 - a.w};
                __stcs(reinterpret_cast<float4*>(orow + 0 * PLANE), o);
            }
            {   // j=1
                float4 o = {c0 - a.y, c1 - a.z, c2 - a.w, c3 - b.x};
                __stcs(reinterpret_cast<float4*>(orow + 1 * PLANE), o);
            }
            {   // j=2
                float4 o = {c0 - a.z, c1 - a.w, c2 - b.x, c3 - b.y};
                __stcs(reinterpret_cast<float4*>(orow + 2 * PLANE), o);
            }
            {   // j=3
                float4 o = {c0 - a.w, c1 - b.x, c2 - b.y, c3 - b.z};
                __stcs(reinterpret_cast<float4*>(orow + 3 * PLANE), o);
            }
            {   // j=4
                float4 o = {c0 - b.x, c1 - b.y, c2 - b.z, c3 - b.w};
                __stcs(reinterpret_cast<float4*>(orow + 4 * PLANE), o);
            }
            {   // j=5
                float4 o = {c0 - b.y, c1 - b.z, c2 - b.w, c3 - cq.x};
                __stcs(reinterpret_cast<float4*>(orow + 5 * PLANE), o);
            }
            {   // j=6
                float4 o = {c0 - b.z, c1 - b.w, c2 - cq.x, c3 - cq.y};
                __stcs(reinterpret_cast<float4*>(orow + 6 * PLANE), o);
            }
        }
    }
}

extern "C" void kernel_launch(void* const* d_in, const int* in_sizes, int n_in,
                              void* d_out, int out_size) {
    const float* x = (const float*)d_in[0];
    float* out = (float*)d_out;
    Subtraction_68212670595965_kernel<<<1024, NTHREADS>>>(x, out);
}

// round 5
// speedup vs baseline: 1.0405x; 1.0405x over previous
#include <cuda_runtime.h>
#include <cuda_bf16.h>

// out[n,c,k,l] = x[n,c,oh,ow] - xpad[n,c,oh+i,ow+j]; K=7, PAD=3
// x:(16,64,56,56) f32 -> out:(16,64,49,3136) f32. HBM-write-bound (~629MB out),
// measured at ~6.6 TB/s effective = the path-independent LTS chip cap.
//
// R4: R2 store loop verbatim (best: 97.7us). Staging vectorized: float4
// zero-fill, then LDG.128 of input rows (224B rows are 16B-aligned) with
// shifted scalar STS for the +3 halo offset. ~4x fewer staging LDGs.

#define PLANE   3136        // 56*56
#define TPITCH  64          // padded pitch (16B-aligned rows)
#define TROWS   62          // 56 + 2*3
#define NTHREADS 256
#define NGROUPS 784         // 3136 / 4 float4-groups per k

__global__ __launch_bounds__(NTHREADS, 1)
void Subtraction_68212670595965_kernel(const float* __restrict__ x,
                                       float* __restrict__ out) {
    __shared__ float tile[TROWS * TPITCH];   // 62*64*4 = 15872 B

    const int nc = blockIdx.x;               // n*64 + c, 0..1023
    const float* __restrict__ xin = x + (size_t)nc * PLANE;
    float* __restrict__ outb = out + (size_t)nc * 49 * PLANE;

    const int tid = threadIdx.x;

    // Phase 1: zero the whole tile with STS.128 (992 float4 / 256 thr).
    {
        float4 z = {0.f, 0.f, 0.f, 0.f};
        float4* t4 = reinterpret_cast<float4*>(tile);
        #pragma unroll
        for (int it = 0; it < 4; ++it) {
            int idx = tid + it * NTHREADS;
            if (idx < (TROWS * TPITCH) / 4) t4[idx] = z;
        }
    }
    __syncthreads();

    // Phase 2: interior fill. 56 rows x 14 float4 = 784 vector loads.
    // Input rows are 224B (16B-aligned); tile dst is shifted +3 (halo) so
    // scatter with 4 scalar STS.
    #pragma unroll 1
    for (int idx = tid; idx < 56 * 14; idx += NTHREADS) {
        const int r  = idx / 14;          // input row 0..55
        const int c4 = idx - r * 14;      // float4 index within row
        const float4 v = reinterpret_cast<const float4*>(xin + r * 56)[c4];
        float* dst = &tile[(r + 3) * TPITCH + 3 + c4 * 4];
        dst[0] = v.x; dst[1] = v.y; dst[2] = v.z; dst[3] = v.w;
    }
    __syncthreads();

    // Store phase: identical to R2 (97.7us best).
    #pragma unroll 1
    for (int g = tid; g < NGROUPS; g += NTHREADS) {
        const int oh  = g / 14;
        const int ow4 = (g - oh * 14) * 4;          // 0,4,...,52

        const int cbase = (oh + 3) * TPITCH + ow4 + 3;
        const float c0 = tile[cbase + 0];
        const float c1 = tile[cbase + 1];
        const float c2 = tile[cbase + 2];
        const float c3 = tile[cbase + 3];

        float* __restrict__ op = outb + 4 * g;

        #pragma unroll
        for (int i = 0; i < 7; ++i) {
            const float4* rp =
                reinterpret_cast<const float4*>(&tile[(oh + i) * TPITCH + ow4]);
            const float4 a = rp[0];
            const float4 b = rp[1];
            const float4 cq = rp[2];
            const float r[12] = {a.x, a.y, a.z, a.w,
                                 b.x, b.y, b.z, b.w,
                                 cq.x, cq.y, cq.z, cq.w};
            #pragma unroll
            for (int j = 0; j < 7; ++j) {
                float4 o;
                o.x = c0 - r[j + 0];
                o.y = c1 - r[j + 1];
                o.z = c2 - r[j + 2];
                o.w = c3 - r[j + 3];
                __stcs(reinterpret_cast<float4*>(op + (i * 7 + j) * PLANE), o);
            }
        }
    }
}

extern "C" void kernel_launch(void* const* d_in, const int* in_sizes, int n_in,
                              void* d_out, int out_size) {
    const float* x = (const float*)d_in[0];
    float* out = (float*)d_out;
    Subtraction_68212670595965_kernel<<<1024, NTHREADS>>>(x, out);
}